// round 13
// baseline (speedup 1.0000x reference)
#include <cuda_runtime.h>
#include <cuda_fp16.h>
#include <cuda_bf16.h>

// ---------------------------------------------------------------------------
// GAT layer. R13 design:
//  - padded bucket CSR (atomic cursor)
//  - fp16 tensor-core GEMM (mma.m16n8k16, fp32 accum); epilogue stores h fp32
//    and a_src/a_dst (prescaled by log2e) from fp32 accumulators
//  - gat_k: 32-edge chunks (lane-parallel exp2 weight phase, smem staging);
//    serial gather loop = shfl + LDS + LDG.128(fp32) + 4 FFMA per edge,
//    unrolled x2 with batched loads (MLP=2).  NO fp16 conversions in loop.
//  - scatter on a side stream concurrent with GEMM (fork/join via events)
// ---------------------------------------------------------------------------

#define N_MAX 50000
#define E_MAX 1600000
#define CH 128
#define HEADS 4
#define MAXDEG 128
#define LOG2E 1.4426950408889634f

__device__ float g_hf[N_MAX * CH];           // 25.6 MB fp32 h (L2-resident)
__device__ float g_as[N_MAX * HEADS];        // a_src * LOG2E
__device__ float g_ad[N_MAX * HEADS];        // a_dst * LOG2E
__device__ int   g_cnt[N_MAX];
__device__ int   g_pad[N_MAX * MAXDEG];      // padded edge buckets (src ids)

// ---------------------------------------------------------------------------
__device__ __forceinline__ float lrelu(float x) {
    return fmaxf(x, 0.2f * x);
}
__device__ __forceinline__ float ex2(float x) {
    float r;
    asm("ex2.approx.ftz.f32 %0, %1;" : "=f"(r) : "f"(x));
    return r;
}
__device__ __forceinline__ float sel4(float4 v, int hd) {
    float r = v.x;
    if (hd == 1) r = v.y;
    else if (hd == 2) r = v.z;
    else if (hd == 3) r = v.w;
    return r;
}

// ---------------------------------------------------------------------------
// bucket build
// ---------------------------------------------------------------------------
__global__ void zero_cnt_k(int nodes) {
    int i = blockIdx.x * blockDim.x + threadIdx.x;
    if (i < nodes) g_cnt[i] = 0;
}

__global__ void scatter_pad_k(const int* __restrict__ src,
                              const int* __restrict__ dst, int E) {
    int e = blockIdx.x * blockDim.x + threadIdx.x;
    if (e < E) {
        int d = dst[e];
        int p = atomicAdd(&g_cnt[d], 1);
        if (p < MAXDEG) g_pad[d * MAXDEG + p] = src[e];
    }
}

// ---------------------------------------------------------------------------
// fp16 MMA GEMM: h = x @ W  (M x 128)(128 x 128), fp32 accum.
// ---------------------------------------------------------------------------
#define GBM 128
#define APITCH 136
#define GEMM_SMEM (2 * 128 * APITCH * 2)

__global__ __launch_bounds__(256) void hgemm_k(const float* __restrict__ X,
                                               const float* __restrict__ W,
                                               const float* __restrict__ att_src,
                                               const float* __restrict__ att_dst,
                                               int M) {
    extern __shared__ __half sm[];
    __half* sA = sm;                     // x tile, row-major, pitch 136
    __half* sB = sm + 128 * APITCH;      // W transposed [n][k], pitch 136

    const int tid = threadIdx.x;
    const int row0 = blockIdx.x * GBM;

#pragma unroll
    for (int i = 0; i < 16; i++) {
        int idx = tid + i * 256;
        int r = idx >> 5;
        int c = (idx & 31) * 4;
        float4 v = make_float4(0.f, 0.f, 0.f, 0.f);
        if (row0 + r < M) v = *(const float4*)(X + (size_t)(row0 + r) * CH + c);
        __half2* dp = (__half2*)(sA + r * APITCH + c);
        dp[0] = __floats2half2_rn(v.x, v.y);
        dp[1] = __floats2half2_rn(v.z, v.w);
    }
#pragma unroll
    for (int i = 0; i < 16; i++) {
        int idx = tid + i * 256;
        int k = idx >> 5;
        int n = (idx & 31) * 4;
        float4 v = *(const float4*)(W + k * CH + n);
        sB[(n + 0) * APITCH + k] = __float2half(v.x);
        sB[(n + 1) * APITCH + k] = __float2half(v.y);
        sB[(n + 2) * APITCH + k] = __float2half(v.z);
        sB[(n + 3) * APITCH + k] = __float2half(v.w);
    }
    __syncthreads();

    const int warp = tid >> 5, lane = tid & 31;
    const int q = lane & 3, p = lane >> 2;
    const int r0 = warp * 16;

    float acc[16][4];
#pragma unroll
    for (int j = 0; j < 16; j++)
#pragma unroll
        for (int c = 0; c < 4; c++) acc[j][c] = 0.f;

#pragma unroll
    for (int kk = 0; kk < 8; kk++) {
        int kb = kk * 16;
        unsigned a0 = *(const unsigned*)(sA + (r0 + p) * APITCH + kb + 2 * q);
        unsigned a1 = *(const unsigned*)(sA + (r0 + p + 8) * APITCH + kb + 2 * q);
        unsigned a2 = *(const unsigned*)(sA + (r0 + p) * APITCH + kb + 2 * q + 8);
        unsigned a3 = *(const unsigned*)(sA + (r0 + p + 8) * APITCH + kb + 2 * q + 8);
#pragma unroll
        for (int j = 0; j < 16; j++) {
            unsigned b0 = *(const unsigned*)(sB + (8 * j + p) * APITCH + kb + 2 * q);
            unsigned b1 = *(const unsigned*)(sB + (8 * j + p) * APITCH + kb + 2 * q + 8);
            asm volatile(
                "mma.sync.aligned.m16n8k16.row.col.f32.f16.f16.f32 "
                "{%0,%1,%2,%3}, {%4,%5,%6,%7}, {%8,%9}, {%0,%1,%2,%3};"
                : "+f"(acc[j][0]), "+f"(acc[j][1]), "+f"(acc[j][2]), "+f"(acc[j][3])
                : "r"(a0), "r"(a1), "r"(a2), "r"(a3), "r"(b0), "r"(b1));
        }
    }

    int grow_lo = row0 + r0 + p;
    int grow_hi = grow_lo + 8;
    bool ok_lo = grow_lo < M, ok_hi = grow_hi < M;

    float as_lo[HEADS], as_hi[HEADS], ad_lo[HEADS], ad_hi[HEADS];
#pragma unroll
    for (int h = 0; h < HEADS; h++) { as_lo[h] = as_hi[h] = ad_lo[h] = ad_hi[h] = 0.f; }

#pragma unroll
    for (int j = 0; j < 16; j++) {
        int col = 8 * j + 2 * q;
        int hh = j >> 2;
        float s0 = __ldg(&att_src[col]), s1 = __ldg(&att_src[col + 1]);
        float d0 = __ldg(&att_dst[col]), d1 = __ldg(&att_dst[col + 1]);
        as_lo[hh] += acc[j][0] * s0 + acc[j][1] * s1;
        as_hi[hh] += acc[j][2] * s0 + acc[j][3] * s1;
        ad_lo[hh] += acc[j][0] * d0 + acc[j][1] * d1;
        ad_hi[hh] += acc[j][2] * d0 + acc[j][3] * d1;
        if (ok_lo) {
            float2 v = make_float2(acc[j][0], acc[j][1]);
            *(float2*)(g_hf + (size_t)grow_lo * CH + col) = v;
        }
        if (ok_hi) {
            float2 v = make_float2(acc[j][2], acc[j][3]);
            *(float2*)(g_hf + (size_t)grow_hi * CH + col) = v;
        }
    }
#pragma unroll
    for (int off = 1; off <= 2; off <<= 1) {
#pragma unroll
        for (int h = 0; h < HEADS; h++) {
            as_lo[h] += __shfl_xor_sync(0xffffffffu, as_lo[h], off);
            as_hi[h] += __shfl_xor_sync(0xffffffffu, as_hi[h], off);
            ad_lo[h] += __shfl_xor_sync(0xffffffffu, ad_lo[h], off);
            ad_hi[h] += __shfl_xor_sync(0xffffffffu, ad_hi[h], off);
        }
    }
    if (q == 0) {
        if (ok_lo) {
#pragma unroll
            for (int h = 0; h < HEADS; h++) {
                g_as[grow_lo * HEADS + h] = as_lo[h] * LOG2E;
                g_ad[grow_lo * HEADS + h] = ad_lo[h] * LOG2E;
            }
        }
        if (ok_hi) {
#pragma unroll
            for (int h = 0; h < HEADS; h++) {
                g_as[grow_hi * HEADS + h] = as_hi[h] * LOG2E;
                g_ad[grow_hi * HEADS + h] = ad_hi[h] * LOG2E;
            }
        }
    }
}

// ---------------------------------------------------------------------------
// gat_k: warp per node.  32-edge chunks: lane-parallel weight phase (4 heads,
// exp2), weights staged to smem; serial gather loop unrolled by 2 with
// batched fp32 loads (MLP=2): 2x shfl, 2x LDS, 2x LDG.128, then 8 FFMA.
// No fp16 conversions anywhere in the loop.
// ---------------------------------------------------------------------------
#define GWPB 4   // warps per block (128 threads)

__global__ __launch_bounds__(128) void gat_k(const float* __restrict__ bias,
                                             const float* __restrict__ gamma,
                                             const float* __restrict__ beta,
                                             float* __restrict__ out, int nodes) {
    const unsigned FULL = 0xffffffffu;
    __shared__ float s_w[GWPB][128];

    int warp_in_blk = threadIdx.x >> 5;
    int node = blockIdx.x * GWPB + warp_in_blk;
    int lane = threadIdx.x & 31;
    if (node >= nodes) return;
    int hd = lane >> 3;
    float* swp = s_w[warp_in_blk];

    int deg = g_cnt[node];
    if (deg > MAXDEG) deg = MAXDEG;
    int base = node * MAXDEG;

    const float4* as4 = (const float4*)g_as;
    float4 asn = __ldg(&as4[node]);
    float4 adn = __ldg(&((const float4*)g_ad)[node]);

    // self-loop weights (prescaled logits -> ex2)
    float4 wsf;
    wsf.x = ex2(lrelu(asn.x + adn.x));
    wsf.y = ex2(lrelu(asn.y + adn.y));
    wsf.z = ex2(lrelu(asn.z + adn.z));
    wsf.w = ex2(lrelu(asn.w + adn.w));
    float wself = sel4(wsf, hd);

    const float4* h4 = (const float4*)g_hf;
    float4 hv = h4[(size_t)node * 32 + lane];
    float4 acc;
    acc.x = wself * hv.x;
    acc.y = wself * hv.y;
    acc.z = wself * hv.z;
    acc.w = wself * hv.w;

    float4 wsum = make_float4(0.f, 0.f, 0.f, 0.f);

    for (int e0 = 0; e0 < deg; e0 += 32) {
        int idx = e0 + lane;
        int sj = 0;
        bool valid = idx < deg;
        if (valid) sj = g_pad[base + idx];
        // lane-parallel: 4-head weights for this lane's edge
        float4 av = __ldg(&as4[sj]);
        float4 wv;
        wv.x = ex2(lrelu(av.x + adn.x));
        wv.y = ex2(lrelu(av.y + adn.y));
        wv.z = ex2(lrelu(av.z + adn.z));
        wv.w = ex2(lrelu(av.w + adn.w));
        if (!valid) wv = make_float4(0.f, 0.f, 0.f, 0.f);
        wsum.x += wv.x; wsum.y += wv.y; wsum.z += wv.z; wsum.w += wv.w;
        *(float4*)(swp + lane * 4) = wv;
        __syncwarp();

        int nchunk = min(32, deg - e0);
        int k = 0;
#pragma unroll 2
        for (; k + 1 < nchunk; k += 2) {
            // batch both edges' loads before any FMA (explicit MLP=2)
            int s0 = __shfl_sync(FULL, sj, k);
            int s1 = __shfl_sync(FULL, sj, k + 1);
            float w0 = swp[k * 4 + hd];
            float w1 = swp[(k + 1) * 4 + hd];
            float4 xa = h4[(size_t)s0 * 32 + lane];
            float4 xb = h4[(size_t)s1 * 32 + lane];
            acc.x = fmaf(w0, xa.x, acc.x);
            acc.y = fmaf(w0, xa.y, acc.y);
            acc.z = fmaf(w0, xa.z, acc.z);
            acc.w = fmaf(w0, xa.w, acc.w);
            acc.x = fmaf(w1, xb.x, acc.x);
            acc.y = fmaf(w1, xb.y, acc.y);
            acc.z = fmaf(w1, xb.z, acc.z);
            acc.w = fmaf(w1, xb.w, acc.w);
        }
        if (k < nchunk) {
            int s = __shfl_sync(FULL, sj, k);
            float w = swp[k * 4 + hd];
            float4 xa = h4[(size_t)s * 32 + lane];
            acc.x = fmaf(w, xa.x, acc.x);
            acc.y = fmaf(w, xa.y, acc.y);
            acc.z = fmaf(w, xa.z, acc.z);
            acc.w = fmaf(w, xa.w, acc.w);
        }
        __syncwarp();
    }

    // warp-reduce the 4 per-head weight sums
#pragma unroll
    for (int o = 16; o >= 1; o >>= 1) {
        wsum.x += __shfl_xor_sync(FULL, wsum.x, o);
        wsum.y += __shfl_xor_sync(FULL, wsum.y, o);
        wsum.z += __shfl_xor_sync(FULL, wsum.z, o);
        wsum.w += __shfl_xor_sync(FULL, wsum.w, o);
    }
    float ssum = sel4(wsum, hd) + wself;

    float inv = 1.f / (ssum + 1e-16f);
    float4 b4 = ((const float4*)bias)[lane];
    float4 o4;
    o4.x = acc.x * inv + b4.x;
    o4.y = acc.y * inv + b4.y;
    o4.z = acc.z * inv + b4.z;
    o4.w = acc.w * inv + b4.w;

    // LayerNorm over 128 channels
    float psum = o4.x + o4.y + o4.z + o4.w;
#pragma unroll
    for (int o = 16; o >= 1; o >>= 1) psum += __shfl_xor_sync(FULL, psum, o);
    float mean = psum * (1.f / 128.f);
    float dx = o4.x - mean, dy = o4.y - mean, dz = o4.z - mean, dw = o4.w - mean;
    float pvar = dx * dx + dy * dy + dz * dz + dw * dw;
#pragma unroll
    for (int o = 16; o >= 1; o >>= 1) pvar += __shfl_xor_sync(FULL, pvar, o);
    float rstd = rsqrtf(pvar * (1.f / 128.f) + 1e-5f);

    float4 g4 = ((const float4*)gamma)[lane];
    float4 bt4 = ((const float4*)beta)[lane];
    float4 y;
    y.x = dx * rstd * g4.x + bt4.x;
    y.y = dy * rstd * g4.y + bt4.y;
    y.z = dz * rstd * g4.z + bt4.z;
    y.w = dw * rstd * g4.w + bt4.w;
    y.x = (y.x > 0.f) ? y.x : expm1f(y.x);
    y.y = (y.y > 0.f) ? y.y : expm1f(y.y);
    y.z = (y.z > 0.f) ? y.z : expm1f(y.z);
    y.w = (y.w > 0.f) ? y.w : expm1f(y.w);

    ((float4*)out)[node * 32 + lane] = y;
}

// ---------------------------------------------------------------------------
// side stream + events (created at load time; no allocs in kernel_launch)
// ---------------------------------------------------------------------------
static cudaStream_t g_s1 = nullptr;
static cudaEvent_t g_evA = nullptr, g_evB = nullptr;
static bool g_sok = false;
namespace {
struct _StreamInit {
    _StreamInit() {
        if (cudaStreamCreateWithFlags(&g_s1, cudaStreamNonBlocking) == cudaSuccess &&
            cudaEventCreateWithFlags(&g_evA, cudaEventDisableTiming) == cudaSuccess &&
            cudaEventCreateWithFlags(&g_evB, cudaEventDisableTiming) == cudaSuccess) {
            g_sok = true;
        }
        cudaFuncSetAttribute(hgemm_k, cudaFuncAttributeMaxDynamicSharedMemorySize,
                             GEMM_SMEM);
    }
};
_StreamInit _stream_init_obj;
}

// ---------------------------------------------------------------------------
extern "C" void kernel_launch(void* const* d_in, const int* in_sizes, int n_in,
                              void* d_out, int out_size) {
    const float* x = (const float*)d_in[0];
    const int* ei = (const int*)d_in[1];
    const float* W = (const float*)d_in[2];
    const float* att_src = (const float*)d_in[3];
    const float* att_dst = (const float*)d_in[4];
    const float* bias = (const float*)d_in[5];
    const float* gamma = (const float*)d_in[6];
    const float* beta = (const float*)d_in[7];
    float* out = (float*)d_out;

    int nodes = in_sizes[0] / CH;
    int edges = in_sizes[1] / 2;
    if (nodes > N_MAX || edges > E_MAX) return;

    const int* srcp = ei;
    const int* dstp = ei + edges;

    static bool attr_done = false;
    if (!attr_done) {
        cudaFuncSetAttribute(hgemm_k, cudaFuncAttributeMaxDynamicSharedMemorySize,
                             GEMM_SMEM);
        attr_done = true;
    }

    if (g_sok) {
        zero_cnt_k<<<(nodes + 255) / 256, 256>>>(nodes);
        cudaEventRecord(g_evA, 0);
        cudaStreamWaitEvent(g_s1, g_evA, 0);
        scatter_pad_k<<<(edges + 255) / 256, 256, 0, g_s1>>>(srcp, dstp, edges);
        cudaEventRecord(g_evB, g_s1);
        hgemm_k<<<(nodes + GBM - 1) / GBM, 256, GEMM_SMEM>>>(x, W, att_src,
                                                            att_dst, nodes);
        cudaStreamWaitEvent(0, g_evB, 0);
        gat_k<<<(nodes + GWPB - 1) / GWPB, 128>>>(bias, gamma, beta, out, nodes);
    } else {
        zero_cnt_k<<<(nodes + 255) / 256, 256>>>(nodes);
        scatter_pad_k<<<(edges + 255) / 256, 256>>>(srcp, dstp, edges);
        hgemm_k<<<(nodes + GBM - 1) / GBM, 256, GEMM_SMEM>>>(x, W, att_src,
                                                            att_dst, nodes);
        gat_k<<<(nodes + GWPB - 1) / GWPB, 128>>>(bias, gamma, beta, out, nodes);
    }
}

// round 14
// speedup vs baseline: 1.0500x; 1.0500x over previous
#include <cuda_runtime.h>
#include <cuda_fp16.h>
#include <cuda_bf16.h>

// ---------------------------------------------------------------------------
// GAT layer. R14 design:
//  - padded bucket CSR (atomic cursor); g_cnt zeroed via cudaMemsetAsync
//  - fp16 tensor-core GEMM (mma.m16n8k16, fp32 accum); epilogue stores h fp16
//    and a_src/a_dst (prescaled by log2e) from fp32 accumulators
//  - gat_k: HALF-WARP edge pairing — each lane owns 8 channels (uint4 fp16),
//    a row spans 16 lanes, warp processes 2 edges per iteration. Weight phase
//    stores (w_head, src) pairs in smem, so the serial loop is just
//    LDS.64 + IMAD + LDG.128 + 8 F2F + 8 FFMA per 2 lanes-halves (per edge
//    the warp issues ~11 instrs vs ~15 in R12). Unrolled x2 (4 edges) for MLP.
//  - scatter on a side stream concurrent with GEMM (fork/join via events)
// ---------------------------------------------------------------------------

#define N_MAX 50000
#define E_MAX 1600000
#define CH 128
#define HEADS 4
#define MAXDEG 128
#define LOG2E 1.4426950408889634f

__device__ __half g_hh[N_MAX * CH];          // 12.8 MB fp16 h (L2-resident)
__device__ float  g_as[N_MAX * HEADS];       // a_src * LOG2E
__device__ float  g_ad[N_MAX * HEADS];       // a_dst * LOG2E
__device__ int    g_cnt[N_MAX];
__device__ int    g_pad[N_MAX * MAXDEG];     // padded edge buckets (src ids)

// ---------------------------------------------------------------------------
__device__ __forceinline__ float lrelu(float x) {
    return fmaxf(x, 0.2f * x);
}
__device__ __forceinline__ float ex2(float x) {
    float r;
    asm("ex2.approx.ftz.f32 %0, %1;" : "=f"(r) : "f"(x));
    return r;
}
__device__ __forceinline__ float sel4(float4 v, int hd) {
    float r = v.x;
    if (hd == 1) r = v.y;
    else if (hd == 2) r = v.z;
    else if (hd == 3) r = v.w;
    return r;
}

// ---------------------------------------------------------------------------
// bucket build
// ---------------------------------------------------------------------------
__global__ void zero_cnt_k(int nodes) {
    int i = blockIdx.x * blockDim.x + threadIdx.x;
    if (i < nodes) g_cnt[i] = 0;
}

__global__ void scatter_pad_k(const int* __restrict__ src,
                              const int* __restrict__ dst, int E) {
    int e = blockIdx.x * blockDim.x + threadIdx.x;
    if (e < E) {
        int d = dst[e];
        int p = atomicAdd(&g_cnt[d], 1);
        if (p < MAXDEG) g_pad[d * MAXDEG + p] = src[e];
    }
}

// ---------------------------------------------------------------------------
// fp16 MMA GEMM: h = x @ W  (M x 128)(128 x 128), fp32 accum. (proven R12)
// ---------------------------------------------------------------------------
#define GBM 128
#define APITCH 136
#define GEMM_SMEM (2 * 128 * APITCH * 2)

__global__ __launch_bounds__(256) void hgemm_k(const float* __restrict__ X,
                                               const float* __restrict__ W,
                                               const float* __restrict__ att_src,
                                               const float* __restrict__ att_dst,
                                               int M) {
    extern __shared__ __half sm[];
    __half* sA = sm;                     // x tile, row-major, pitch 136
    __half* sB = sm + 128 * APITCH;      // W transposed [n][k], pitch 136

    const int tid = threadIdx.x;
    const int row0 = blockIdx.x * GBM;

#pragma unroll
    for (int i = 0; i < 16; i++) {
        int idx = tid + i * 256;
        int r = idx >> 5;
        int c = (idx & 31) * 4;
        float4 v = make_float4(0.f, 0.f, 0.f, 0.f);
        if (row0 + r < M) v = *(const float4*)(X + (size_t)(row0 + r) * CH + c);
        __half2* dp = (__half2*)(sA + r * APITCH + c);
        dp[0] = __floats2half2_rn(v.x, v.y);
        dp[1] = __floats2half2_rn(v.z, v.w);
    }
#pragma unroll
    for (int i = 0; i < 16; i++) {
        int idx = tid + i * 256;
        int k = idx >> 5;
        int n = (idx & 31) * 4;
        float4 v = *(const float4*)(W + k * CH + n);
        sB[(n + 0) * APITCH + k] = __float2half(v.x);
        sB[(n + 1) * APITCH + k] = __float2half(v.y);
        sB[(n + 2) * APITCH + k] = __float2half(v.z);
        sB[(n + 3) * APITCH + k] = __float2half(v.w);
    }
    __syncthreads();

    const int warp = tid >> 5, lane = tid & 31;
    const int q = lane & 3, p = lane >> 2;
    const int r0 = warp * 16;

    float acc[16][4];
#pragma unroll
    for (int j = 0; j < 16; j++)
#pragma unroll
        for (int c = 0; c < 4; c++) acc[j][c] = 0.f;

#pragma unroll
    for (int kk = 0; kk < 8; kk++) {
        int kb = kk * 16;
        unsigned a0 = *(const unsigned*)(sA + (r0 + p) * APITCH + kb + 2 * q);
        unsigned a1 = *(const unsigned*)(sA + (r0 + p + 8) * APITCH + kb + 2 * q);
        unsigned a2 = *(const unsigned*)(sA + (r0 + p) * APITCH + kb + 2 * q + 8);
        unsigned a3 = *(const unsigned*)(sA + (r0 + p + 8) * APITCH + kb + 2 * q + 8);
#pragma unroll
        for (int j = 0; j < 16; j++) {
            unsigned b0 = *(const unsigned*)(sB + (8 * j + p) * APITCH + kb + 2 * q);
            unsigned b1 = *(const unsigned*)(sB + (8 * j + p) * APITCH + kb + 2 * q + 8);
            asm volatile(
                "mma.sync.aligned.m16n8k16.row.col.f32.f16.f16.f32 "
                "{%0,%1,%2,%3}, {%4,%5,%6,%7}, {%8,%9}, {%0,%1,%2,%3};"
                : "+f"(acc[j][0]), "+f"(acc[j][1]), "+f"(acc[j][2]), "+f"(acc[j][3])
                : "r"(a0), "r"(a1), "r"(a2), "r"(a3), "r"(b0), "r"(b1));
        }
    }

    int grow_lo = row0 + r0 + p;
    int grow_hi = grow_lo + 8;
    bool ok_lo = grow_lo < M, ok_hi = grow_hi < M;

    float as_lo[HEADS], as_hi[HEADS], ad_lo[HEADS], ad_hi[HEADS];
#pragma unroll
    for (int h = 0; h < HEADS; h++) { as_lo[h] = as_hi[h] = ad_lo[h] = ad_hi[h] = 0.f; }

#pragma unroll
    for (int j = 0; j < 16; j++) {
        int col = 8 * j + 2 * q;
        int hh = j >> 2;
        float s0 = __ldg(&att_src[col]), s1 = __ldg(&att_src[col + 1]);
        float d0 = __ldg(&att_dst[col]), d1 = __ldg(&att_dst[col + 1]);
        as_lo[hh] += acc[j][0] * s0 + acc[j][1] * s1;
        as_hi[hh] += acc[j][2] * s0 + acc[j][3] * s1;
        ad_lo[hh] += acc[j][0] * d0 + acc[j][1] * d1;
        ad_hi[hh] += acc[j][2] * d0 + acc[j][3] * d1;
        if (ok_lo)
            *(__half2*)(g_hh + (size_t)grow_lo * CH + col) =
                __floats2half2_rn(acc[j][0], acc[j][1]);
        if (ok_hi)
            *(__half2*)(g_hh + (size_t)grow_hi * CH + col) =
                __floats2half2_rn(acc[j][2], acc[j][3]);
    }
#pragma unroll
    for (int off = 1; off <= 2; off <<= 1) {
#pragma unroll
        for (int h = 0; h < HEADS; h++) {
            as_lo[h] += __shfl_xor_sync(0xffffffffu, as_lo[h], off);
            as_hi[h] += __shfl_xor_sync(0xffffffffu, as_hi[h], off);
            ad_lo[h] += __shfl_xor_sync(0xffffffffu, ad_lo[h], off);
            ad_hi[h] += __shfl_xor_sync(0xffffffffu, ad_hi[h], off);
        }
    }
    if (q == 0) {
        if (ok_lo) {
#pragma unroll
            for (int h = 0; h < HEADS; h++) {
                g_as[grow_lo * HEADS + h] = as_lo[h] * LOG2E;
                g_ad[grow_lo * HEADS + h] = ad_lo[h] * LOG2E;
            }
        }
        if (ok_hi) {
#pragma unroll
            for (int h = 0; h < HEADS; h++) {
                g_as[grow_hi * HEADS + h] = as_hi[h] * LOG2E;
                g_ad[grow_hi * HEADS + h] = ad_hi[h] * LOG2E;
            }
        }
    }
}

// ---------------------------------------------------------------------------
// gat_k: warp per node, HALF-WARP edge pairing.
//  lane = (sub, hw): sub = lane>>4 selects which edge of a pair, hw = lane&15
//  owns channels hw*8 .. hw*8+7 (uint4 of fp16). Weight phase stores
//  {w_head, src_bits} float2 per (edge, head) in smem; serial loop per 2
//  edges: 2x LDS.64 + 2x LDG.128 + 16 F2F + 16 FFMA (unrolled x2 for MLP).
//  Halves combined via shfl_xor(16); then narrow to 4 ch/lane and reuse the
//  proven LN/ELU epilogue.
// ---------------------------------------------------------------------------
#define GWPB 4   // warps per block (128 threads)

__global__ __launch_bounds__(128) void gat_k(const float* __restrict__ bias,
                                             const float* __restrict__ gamma,
                                             const float* __restrict__ beta,
                                             float* __restrict__ out, int nodes) {
    const unsigned FULL = 0xffffffffu;
    __shared__ float2 s_w[GWPB][128];   // [edge(32)][head(4)] = {w, src_bits}

    int warp_in_blk = threadIdx.x >> 5;
    int node = blockIdx.x * GWPB + warp_in_blk;
    int lane = threadIdx.x & 31;
    if (node >= nodes) return;

    int sub = lane >> 4;        // which edge of the pair
    int hw = lane & 15;         // channel group: ch = hw*8 .. +7
    int hd2 = hw >> 2;          // head of those channels
    float2* swp = s_w[warp_in_blk];

    int deg = g_cnt[node];
    if (deg > MAXDEG) deg = MAXDEG;
    int base = node * MAXDEG;

    const float4* as4 = (const float4*)g_as;
    float4 asn = __ldg(&as4[node]);
    float4 adn = __ldg(&((const float4*)g_ad)[node]);

    // self-loop weights (prescaled logits -> ex2)
    float4 wsf;
    wsf.x = ex2(lrelu(asn.x + adn.x));
    wsf.y = ex2(lrelu(asn.y + adn.y));
    wsf.z = ex2(lrelu(asn.z + adn.z));
    wsf.w = ex2(lrelu(asn.w + adn.w));
    float wself = sel4(wsf, hd2);

    const __half* hbase = g_hh;

    float acc[8];
#pragma unroll
    for (int i = 0; i < 8; i++) acc[i] = 0.f;

    float4 wsum = make_float4(0.f, 0.f, 0.f, 0.f);

    for (int e0 = 0; e0 < deg; e0 += 32) {
        // ---- lane-parallel weight phase (lane = edge within chunk) ----
        int idx = e0 + lane;
        int sj = 0;
        bool valid = idx < deg;
        if (valid) sj = g_pad[base + idx];
        float4 av = __ldg(&as4[sj]);
        float4 wv;
        wv.x = ex2(lrelu(av.x + adn.x));
        wv.y = ex2(lrelu(av.y + adn.y));
        wv.z = ex2(lrelu(av.z + adn.z));
        wv.w = ex2(lrelu(av.w + adn.w));
        if (!valid) wv = make_float4(0.f, 0.f, 0.f, 0.f);
        wsum.x += wv.x; wsum.y += wv.y; wsum.z += wv.z; wsum.w += wv.w;
        float srcf = __int_as_float(sj);
        // swp[e*4+h] = {w_h, srcf}; write as two STS.128
        *(float4*)(&swp[lane * 4 + 0]) = make_float4(wv.x, srcf, wv.y, srcf);
        *(float4*)(&swp[lane * 4 + 2]) = make_float4(wv.z, srcf, wv.w, srcf);
        __syncwarp();

        int nchunk = min(32, deg - e0);
        int k = 0;
        // main: 4 edges per iteration (2 per half-warp pass, x2 for MLP)
        for (; k + 3 < nchunk; k += 4) {
            float2 pA = swp[(k + sub) * 4 + hd2];
            float2 pB = swp[(k + 2 + sub) * 4 + hd2];
            uint4 gA = *(const uint4*)(hbase +
                        (size_t)__float_as_int(pA.y) * CH + hw * 8);
            uint4 gB = *(const uint4*)(hbase +
                        (size_t)__float_as_int(pB.y) * CH + hw * 8);
            float wA = pA.x, wB = pB.x;
            float2 t;
            t = __half22float2(*(__half2*)&gA.x);
            acc[0] = fmaf(wA, t.x, acc[0]); acc[1] = fmaf(wA, t.y, acc[1]);
            t = __half22float2(*(__half2*)&gA.y);
            acc[2] = fmaf(wA, t.x, acc[2]); acc[3] = fmaf(wA, t.y, acc[3]);
            t = __half22float2(*(__half2*)&gA.z);
            acc[4] = fmaf(wA, t.x, acc[4]); acc[5] = fmaf(wA, t.y, acc[5]);
            t = __half22float2(*(__half2*)&gA.w);
            acc[6] = fmaf(wA, t.x, acc[6]); acc[7] = fmaf(wA, t.y, acc[7]);
            t = __half22float2(*(__half2*)&gB.x);
            acc[0] = fmaf(wB, t.x, acc[0]); acc[1] = fmaf(wB, t.y, acc[1]);
            t = __half22float2(*(__half2*)&gB.y);
            acc[2] = fmaf(wB, t.x, acc[2]); acc[3] = fmaf(wB, t.y, acc[3]);
            t = __half22float2(*(__half2*)&gB.z);
            acc[4] = fmaf(wB, t.x, acc[4]); acc[5] = fmaf(wB, t.y, acc[5]);
            t = __half22float2(*(__half2*)&gB.w);
            acc[6] = fmaf(wB, t.x, acc[6]); acc[7] = fmaf(wB, t.y, acc[7]);
        }
        // tail pairs: slots beyond nchunk hold w=0 (safe: all 32 slots written)
        for (; k < nchunk; k += 2) {
            float2 p = swp[(k + sub) * 4 + hd2];
            uint4 g = *(const uint4*)(hbase +
                       (size_t)__float_as_int(p.y) * CH + hw * 8);
            float w = p.x;
            float2 t;
            t = __half22float2(*(__half2*)&g.x);
            acc[0] = fmaf(w, t.x, acc[0]); acc[1] = fmaf(w, t.y, acc[1]);
            t = __half22float2(*(__half2*)&g.y);
            acc[2] = fmaf(w, t.x, acc[2]); acc[3] = fmaf(w, t.y, acc[3]);
            t = __half22float2(*(__half2*)&g.z);
            acc[4] = fmaf(w, t.x, acc[4]); acc[5] = fmaf(w, t.y, acc[5]);
            t = __half22float2(*(__half2*)&g.w);
            acc[6] = fmaf(w, t.x, acc[6]); acc[7] = fmaf(w, t.y, acc[7]);
        }
        __syncwarp();
    }

    // combine the two half-warp partial sums (same channels, partner lane)
#pragma unroll
    for (int i = 0; i < 8; i++) acc[i] += __shfl_xor_sync(FULL, acc[i], 16);

    // narrow to 4 channels per lane: float4 index c4 = hw*2 + sub
    int c4 = hw * 2 + sub;
    float4 o4;
    if (sub == 0) o4 = make_float4(acc[0], acc[1], acc[2], acc[3]);
    else          o4 = make_float4(acc[4], acc[5], acc[6], acc[7]);

    // self contribution on the narrowed channels
    {
        uint2 hs = *(const uint2*)(hbase + (size_t)node * CH + c4 * 4);
        float2 u0 = __half22float2(*(__half2*)&hs.x);
        float2 u1 = __half22float2(*(__half2*)&hs.y);
        o4.x = fmaf(wself, u0.x, o4.x);
        o4.y = fmaf(wself, u0.y, o4.y);
        o4.z = fmaf(wself, u1.x, o4.z);
        o4.w = fmaf(wself, u1.y, o4.w);
    }

    // warp-reduce the 4 per-head weight sums
#pragma unroll
    for (int o = 16; o >= 1; o >>= 1) {
        wsum.x += __shfl_xor_sync(FULL, wsum.x, o);
        wsum.y += __shfl_xor_sync(FULL, wsum.y, o);
        wsum.z += __shfl_xor_sync(FULL, wsum.z, o);
        wsum.w += __shfl_xor_sync(FULL, wsum.w, o);
    }
    float ssum = sel4(wsum, hd2) + wself;

    float inv = 1.f / (ssum + 1e-16f);
    float4 b4 = ((const float4*)bias)[c4];
    o4.x = o4.x * inv + b4.x;
    o4.y = o4.y * inv + b4.y;
    o4.z = o4.z * inv + b4.z;
    o4.w = o4.w * inv + b4.w;

    // LayerNorm over 128 channels (each channel appears exactly once in warp)
    float psum = o4.x + o4.y + o4.z + o4.w;
#pragma unroll
    for (int o = 16; o >= 1; o >>= 1) psum += __shfl_xor_sync(FULL, psum, o);
    float mean = psum * (1.f / 128.f);
    float dx = o4.x - mean, dy = o4.y - mean, dz = o4.z - mean, dw = o4.w - mean;
    float pvar = dx * dx + dy * dy + dz * dz + dw * dw;
#pragma unroll
    for (int o = 16; o >= 1; o >>= 1) pvar += __shfl_xor_sync(FULL, pvar, o);
    float rstd = rsqrtf(pvar * (1.f / 128.f) + 1e-5f);

    float4 g4 = ((const float4*)gamma)[c4];
    float4 bt4 = ((const float4*)beta)[c4];
    float4 y;
    y.x = dx * rstd * g4.x + bt4.x;
    y.y = dy * rstd * g4.y + bt4.y;
    y.z = dz * rstd * g4.z + bt4.z;
    y.w = dw * rstd * g4.w + bt4.w;
    y.x = (y.x > 0.f) ? y.x : expm1f(y.x);
    y.y = (y.y > 0.f) ? y.y : expm1f(y.y);
    y.z = (y.z > 0.f) ? y.z : expm1f(y.z);
    y.w = (y.w > 0.f) ? y.w : expm1f(y.w);

    ((float4*)out)[node * 32 + c4] = y;
}

// ---------------------------------------------------------------------------
// side stream + events + symbol address (created at load time; no allocs)
// ---------------------------------------------------------------------------
static cudaStream_t g_s1 = nullptr;
static cudaEvent_t g_evA = nullptr, g_evB = nullptr;
static bool g_sok = false;
static void* g_cnt_ptr = nullptr;
namespace {
struct _StreamInit {
    _StreamInit() {
        if (cudaStreamCreateWithFlags(&g_s1, cudaStreamNonBlocking) == cudaSuccess &&
            cudaEventCreateWithFlags(&g_evA, cudaEventDisableTiming) == cudaSuccess &&
            cudaEventCreateWithFlags(&g_evB, cudaEventDisableTiming) == cudaSuccess) {
            g_sok = true;
        }
        cudaGetSymbolAddress(&g_cnt_ptr, g_cnt);
        cudaFuncSetAttribute(hgemm_k, cudaFuncAttributeMaxDynamicSharedMemorySize,
                             GEMM_SMEM);
    }
};
_StreamInit _stream_init_obj;
}

// ---------------------------------------------------------------------------
extern "C" void kernel_launch(void* const* d_in, const int* in_sizes, int n_in,
                              void* d_out, int out_size) {
    const float* x = (const float*)d_in[0];
    const int* ei = (const int*)d_in[1];
    const float* W = (const float*)d_in[2];
    const float* att_src = (const float*)d_in[3];
    const float* att_dst = (const float*)d_in[4];
    const float* bias = (const float*)d_in[5];
    const float* gamma = (const float*)d_in[6];
    const float* beta = (const float*)d_in[7];
    float* out = (float*)d_out;

    int nodes = in_sizes[0] / CH;
    int edges = in_sizes[1] / 2;
    if (nodes > N_MAX || edges > E_MAX) return;

    const int* srcp = ei;
    const int* dstp = ei + edges;

    static bool attr_done = false;
    if (!attr_done) {
        cudaFuncSetAttribute(hgemm_k, cudaFuncAttributeMaxDynamicSharedMemorySize,
                             GEMM_SMEM);
        if (!g_cnt_ptr) cudaGetSymbolAddress(&g_cnt_ptr, g_cnt);
        attr_done = true;
    }

    if (g_sok) {
        // zero counters (memset replaces a kernel), then fork scatter || gemm
        if (g_cnt_ptr)
            cudaMemsetAsync(g_cnt_ptr, 0, (size_t)nodes * sizeof(int), 0);
        else
            zero_cnt_k<<<(nodes + 255) / 256, 256>>>(nodes);
        cudaEventRecord(g_evA, 0);
        cudaStreamWaitEvent(g_s1, g_evA, 0);
        scatter_pad_k<<<(edges + 255) / 256, 256, 0, g_s1>>>(srcp, dstp, edges);
        cudaEventRecord(g_evB, g_s1);
        hgemm_k<<<(nodes + GBM - 1) / GBM, 256, GEMM_SMEM>>>(x, W, att_src,
                                                            att_dst, nodes);
        cudaStreamWaitEvent(0, g_evB, 0);
        gat_k<<<(nodes + GWPB - 1) / GWPB, 128>>>(bias, gamma, beta, out, nodes);
    } else {
        zero_cnt_k<<<(nodes + 255) / 256, 256>>>(nodes);
        scatter_pad_k<<<(edges + 255) / 256, 256>>>(srcp, dstp, edges);
        hgemm_k<<<(nodes + GBM - 1) / GBM, 256, GEMM_SMEM>>>(x, W, att_src,
                                                            att_dst, nodes);
        gat_k<<<(nodes + GWPB - 1) / GWPB, 128>>>(bias, gamma, beta, out, nodes);
    }
}